// round 2
// baseline (speedup 1.0000x reference)
#include <cuda_runtime.h>
#include <math.h>

// ---------------------------------------------------------------------------
// Problem constants
// ---------------------------------------------------------------------------
#define B_   4
#define N_   2048
#define D_   768
#define H_   12
#define HD_  64                    // head dim
#define M_   (B_ * N_)             // 8192 flattened rows
#define QKV_COLS (3 * D_)          // 2304

// Scratch (alloc-free rule: __device__ globals)
__device__ float g_qkv[(size_t)M_ * QKV_COLS];   // [B*N, 3D]  ~75.5 MB
__device__ float g_att[(size_t)M_ * D_];         // [B*N, D]   ~25 MB

// ---------------------------------------------------------------------------
// SGEMM: C[M,N] = A[M,K] @ B[K,N] (+ bias). 128x128 block tile, BK=8,
// 256 threads, 8x8 per thread. All dims multiples of tile sizes here.
// ---------------------------------------------------------------------------
template<bool BIAS>
__global__ __launch_bounds__(256) void sgemm128(
    const float* __restrict__ A, const float* __restrict__ Bm,
    const float* __restrict__ bias, float* __restrict__ C,
    int M, int N, int K)
{
    __shared__ float As[8][128];   // transposed A tile: As[k][m]
    __shared__ float Bs[8][128];   // Bs[k][n]

    const int tid = threadIdx.x;
    const int tx  = tid & 15;      // 0..15 -> 8 cols each
    const int ty  = tid >> 4;      // 0..15 -> 8 rows each
    const int row0 = blockIdx.y * 128;
    const int col0 = blockIdx.x * 128;

    const int arow = tid >> 1;           // 0..127
    const int acol = (tid & 1) * 4;      // 0 or 4
    const int brow = tid >> 5;           // 0..7
    const int bcol = (tid & 31) * 4;     // 0..124

    const float* Aptr = A + (size_t)(row0 + arow) * K + acol;
    const float* Bptr = Bm + (size_t)brow * N + col0 + bcol;

    float acc[8][8];
    #pragma unroll
    for (int i = 0; i < 8; i++)
        #pragma unroll
        for (int j = 0; j < 8; j++) acc[i][j] = 0.f;

    for (int k0 = 0; k0 < K; k0 += 8) {
        float4 av = *(const float4*)(Aptr + k0);
        As[acol + 0][arow] = av.x;
        As[acol + 1][arow] = av.y;
        As[acol + 2][arow] = av.z;
        As[acol + 3][arow] = av.w;
        *(float4*)&Bs[brow][bcol] = *(const float4*)(Bptr + (size_t)k0 * N);
        __syncthreads();

        #pragma unroll
        for (int k = 0; k < 8; k++) {
            float a[8], b[8];
            *(float4*)&a[0] = *(float4*)&As[k][ty * 8];
            *(float4*)&a[4] = *(float4*)&As[k][ty * 8 + 4];
            *(float4*)&b[0] = *(float4*)&Bs[k][tx * 8];
            *(float4*)&b[4] = *(float4*)&Bs[k][tx * 8 + 4];
            #pragma unroll
            for (int i = 0; i < 8; i++)
                #pragma unroll
                for (int j = 0; j < 8; j++)
                    acc[i][j] = fmaf(a[i], b[j], acc[i][j]);
        }
        __syncthreads();
    }

    #pragma unroll
    for (int i = 0; i < 8; i++) {
        const size_t r = (size_t)(row0 + ty * 8 + i) * N;
        #pragma unroll
        for (int j = 0; j < 8; j += 4) {
            const int c = col0 + tx * 8 + j;
            float4 v = make_float4(acc[i][j], acc[i][j+1], acc[i][j+2], acc[i][j+3]);
            if (BIAS) {
                v.x += bias[c + 0]; v.y += bias[c + 1];
                v.z += bias[c + 2]; v.w += bias[c + 3];
            }
            *(float4*)&C[r + c] = v;
        }
    }
}

// ---------------------------------------------------------------------------
// Flash attention, fp32, head_dim=64. Block = 64 query rows of one (b,h).
// 256 threads as 16x16 grid, each thread owns 4 q-rows x 4 cols.
// Shared tiles: Qs[d][r], Ks[d][c], Vs[j][d], Ps[r][c], all 64 x LD.
// ---------------------------------------------------------------------------
#define LD_ 68   // padded leading dim (floats)
#define ATTN_SMEM (4 * 64 * LD_ * (int)sizeof(float))

__global__ __launch_bounds__(256) void attn_kernel(
    const float* __restrict__ qkv, float* __restrict__ out)
{
    extern __shared__ float sm[];
    float* Qs = sm;                  // [d][r]
    float* Ks = sm + 64 * LD_;       // [d][c]
    float* Vs = sm + 2 * 64 * LD_;   // [j][d]
    float* Ps = sm + 3 * 64 * LD_;   // [r][c]

    const int tid = threadIdx.x;
    const int tx = tid & 15;         // col group (4 cols)
    const int ty = tid >> 4;         // row group (4 rows)
    const int qb = blockIdx.x;       // 0..31
    const int bh = blockIdx.y;       // 0..47
    const int b  = bh / H_;
    const int h  = bh % H_;

    const size_t base = (size_t)b * N_ * QKV_COLS;
    const int qoff = h * HD_;
    const int koff = D_ + h * HD_;
    const int voff = 2 * D_ + h * HD_;

    // ---- load Q (transposed to [d][r]), pre-scaled by 1/sqrt(64) ----
    {
        const int r0 = tid >> 4;          // 0..15
        const int d  = (tid & 15) * 4;
        #pragma unroll
        for (int rr = r0; rr < 64; rr += 16) {
            const float4 q = *(const float4*)&qkv[base + (size_t)(qb * 64 + rr) * QKV_COLS + qoff + d];
            Qs[(d + 0) * LD_ + rr] = q.x * 0.125f;
            Qs[(d + 1) * LD_ + rr] = q.y * 0.125f;
            Qs[(d + 2) * LD_ + rr] = q.z * 0.125f;
            Qs[(d + 3) * LD_ + rr] = q.w * 0.125f;
        }
    }

    float m_i[4], l_i[4], O[4][4];
    #pragma unroll
    for (int i = 0; i < 4; i++) {
        m_i[i] = -INFINITY; l_i[i] = 0.f;
        #pragma unroll
        for (int c = 0; c < 4; c++) O[i][c] = 0.f;
    }

    for (int t = 0; t < N_ / 64; t++) {
        __syncthreads();   // protect Ks/Vs from prior-iteration readers
        // ---- load K (transposed [d][c]) and V ([j][d]) ----
        {
            const int r0 = tid >> 4;
            const int d  = (tid & 15) * 4;
            #pragma unroll
            for (int rr = r0; rr < 64; rr += 16) {
                const size_t grow = base + (size_t)(t * 64 + rr) * QKV_COLS;
                const float4 kk = *(const float4*)&qkv[grow + koff + d];
                Ks[(d + 0) * LD_ + rr] = kk.x;
                Ks[(d + 1) * LD_ + rr] = kk.y;
                Ks[(d + 2) * LD_ + rr] = kk.z;
                Ks[(d + 3) * LD_ + rr] = kk.w;
                *(float4*)&Vs[rr * LD_ + d] = *(const float4*)&qkv[grow + voff + d];
            }
        }
        __syncthreads();

        // ---- S = Q @ K^T (64x64x64) ----
        float s[4][4];
        #pragma unroll
        for (int i = 0; i < 4; i++)
            #pragma unroll
            for (int j = 0; j < 4; j++) s[i][j] = 0.f;

        #pragma unroll 4
        for (int d0 = 0; d0 < 64; d0++) {
            const float4 qv = *(const float4*)&Qs[d0 * LD_ + 4 * ty];
            const float4 kk = *(const float4*)&Ks[d0 * LD_ + 4 * tx];
            const float qa[4] = {qv.x, qv.y, qv.z, qv.w};
            const float kb[4] = {kk.x, kk.y, kk.z, kk.w};
            #pragma unroll
            for (int i = 0; i < 4; i++)
                #pragma unroll
                for (int j = 0; j < 4; j++)
                    s[i][j] = fmaf(qa[i], kb[j], s[i][j]);
        }

        // ---- online softmax update ----
        #pragma unroll
        for (int i = 0; i < 4; i++) {
            float rm = fmaxf(fmaxf(s[i][0], s[i][1]), fmaxf(s[i][2], s[i][3]));
            #pragma unroll
            for (int msk = 8; msk >= 1; msk >>= 1)
                rm = fmaxf(rm, __shfl_xor_sync(0xffffffffu, rm, msk));
            const float mnew = fmaxf(m_i[i], rm);
            const float sc = __expf(m_i[i] - mnew);
            float p[4], rs = 0.f;
            #pragma unroll
            for (int j = 0; j < 4; j++) { p[j] = __expf(s[i][j] - mnew); rs += p[j]; }
            #pragma unroll
            for (int msk = 8; msk >= 1; msk >>= 1)
                rs += __shfl_xor_sync(0xffffffffu, rs, msk);
            l_i[i] = l_i[i] * sc + rs;
            m_i[i] = mnew;
            #pragma unroll
            for (int c = 0; c < 4; c++) O[i][c] *= sc;
            *(float4*)&Ps[(4 * ty + i) * LD_ + 4 * tx] = make_float4(p[0], p[1], p[2], p[3]);
        }
        __syncthreads();

        // ---- O += P @ V (64x64x64) ----
        #pragma unroll 4
        for (int j0 = 0; j0 < 64; j0++) {
            const float4 vv = *(const float4*)&Vs[j0 * LD_ + 4 * tx];
            const float vb[4] = {vv.x, vv.y, vv.z, vv.w};
            #pragma unroll
            for (int i = 0; i < 4; i++) {
                const float pr = Ps[(4 * ty + i) * LD_ + j0];
                #pragma unroll
                for (int c = 0; c < 4; c++)
                    O[i][c] = fmaf(pr, vb[c], O[i][c]);
            }
        }
    }

    // ---- finalize + write out in [B,N,D] layout ----
    #pragma unroll
    for (int i = 0; i < 4; i++) {
        const float inv = 1.f / l_i[i];
        const int n = qb * 64 + 4 * ty + i;
        float4 o = make_float4(O[i][0] * inv, O[i][1] * inv, O[i][2] * inv, O[i][3] * inv);
        *(float4*)&out[((size_t)b * N_ + n) * D_ + h * HD_ + 4 * tx] = o;
    }
}

// ---------------------------------------------------------------------------
// Launch
// ---------------------------------------------------------------------------
extern "C" void kernel_launch(void* const* d_in, const int* in_sizes, int n_in,
                              void* d_out, int out_size)
{
    const float* x      = (const float*)d_in[0];
    const float* w_qkv  = (const float*)d_in[1];
    const float* w_proj = (const float*)d_in[2];
    const float* b_proj = (const float*)d_in[3];
    float* out = (float*)d_out;

    float *qkv, *att;
    cudaGetSymbolAddress((void**)&qkv, g_qkv);
    cudaGetSymbolAddress((void**)&att, g_att);

    cudaFuncSetAttribute(attn_kernel, cudaFuncAttributeMaxDynamicSharedMemorySize, ATTN_SMEM);

    // 1) QKV = X @ W_qkv : [8192,768] x [768,2304]
    sgemm128<false><<<dim3(QKV_COLS / 128, M_ / 128), 256>>>(
        x, w_qkv, nullptr, qkv, M_, QKV_COLS, D_);

    // 2) fused flash attention -> [B,N,D]
    attn_kernel<<<dim3(N_ / 64, B_ * H_), 256, ATTN_SMEM>>>(qkv, att);

    // 3) OUT = ATT @ W_proj + b : [8192,768] x [768,768]
    sgemm128<true><<<dim3(D_ / 128, M_ / 128), 256>>>(
        att, w_proj, b_proj, out, M_, D_, D_);
}

// round 4
// speedup vs baseline: 2.4608x; 2.4608x over previous
#include <cuda_runtime.h>
#include <math.h>
#include <stdint.h>

// ---------------------------------------------------------------------------
// Problem constants
// ---------------------------------------------------------------------------
#define B_   4
#define N_   2048
#define D_   768
#define H_   12
#define HD_  64
#define M_   (B_ * N_)             // 8192
#define QKV_COLS (3 * D_)          // 2304

// Scratch (alloc-free rule)
__device__ float g_qkv[(size_t)M_ * QKV_COLS];
__device__ float g_att[(size_t)M_ * D_];

// ---------------------------------------------------------------------------
// tf32 helpers
// ---------------------------------------------------------------------------
__device__ __forceinline__ uint32_t f2tf(float x) {
    uint32_t r;
    asm("cvt.rna.tf32.f32 %0, %1;" : "=r"(r) : "f"(x));
    return r;
}

__device__ __forceinline__ void mma_tf32(float* c, const uint32_t* a, const uint32_t* b) {
    asm volatile(
        "mma.sync.aligned.m16n8k8.row.col.f32.tf32.tf32.f32 "
        "{%0,%1,%2,%3}, {%4,%5,%6,%7}, {%8,%9}, {%0,%1,%2,%3};"
        : "+f"(c[0]), "+f"(c[1]), "+f"(c[2]), "+f"(c[3])
        : "r"(a[0]), "r"(a[1]), "r"(a[2]), "r"(a[3]), "r"(b[0]), "r"(b[1]));
}

// ---------------------------------------------------------------------------
// tf32 tensor-core GEMM: C[M,N] = A[M,K] @ B[K,N] (+bias)
// 128x128 block, BK=32, 256 threads (8 warps, each 32x64).
// ---------------------------------------------------------------------------
#define GLDA 136
#define GLDB 136

template<bool BIAS>
__global__ __launch_bounds__(256) void gemm_tc(
    const float* __restrict__ A, const float* __restrict__ Bm,
    const float* __restrict__ bias, float* __restrict__ C,
    int M, int N, int K)
{
    __shared__ uint32_t As[32 * GLDA];   // transposed: As[k][m]
    __shared__ uint32_t Bs[32 * GLDB];   // Bs[k][n]

    const int tid  = threadIdx.x;
    const int lane = tid & 31;
    const int wid  = tid >> 5;
    const int g    = lane >> 2;          // groupID
    const int tg   = lane & 3;           // threadID in group
    const int wm   = wid & 3;            // warp row  (4)
    const int wn   = wid >> 2;           // warp col  (2)
    const int row0 = blockIdx.y * 128;
    const int col0 = blockIdx.x * 128;

    float acc[2][8][4];
    #pragma unroll
    for (int mt = 0; mt < 2; mt++)
        #pragma unroll
        for (int nt = 0; nt < 8; nt++)
            #pragma unroll
            for (int i = 0; i < 4; i++) acc[mt][nt][i] = 0.f;

    const int am  = tid & 127;           // A row
    const int akb = (tid >> 7) * 4;      // A k base (0 or 4)
    const int bk  = tid >> 3;            // B k row (0..31)
    const int bnb = (tid & 7) * 16;      // B n base

    const float* Ap = A + (size_t)(row0 + am) * K;
    const float* Bp = Bm + (size_t)bk * N + col0;

    for (int k0 = 0; k0 < K; k0 += 32) {
        #pragma unroll
        for (int i = 0; i < 4; i++) {
            const int k = akb + i * 8;
            float4 v = *(const float4*)(Ap + k0 + k);
            As[(k + 0) * GLDA + am] = f2tf(v.x);
            As[(k + 1) * GLDA + am] = f2tf(v.y);
            As[(k + 2) * GLDA + am] = f2tf(v.z);
            As[(k + 3) * GLDA + am] = f2tf(v.w);
        }
        #pragma unroll
        for (int i = 0; i < 4; i++) {
            const int n = bnb + i * 4;
            float4 v = *(const float4*)(Bp + (size_t)k0 * N + n);
            uint4 u = make_uint4(f2tf(v.x), f2tf(v.y), f2tf(v.z), f2tf(v.w));
            *(uint4*)&Bs[bk * GLDB + n] = u;
        }
        __syncthreads();

        #pragma unroll
        for (int ks = 0; ks < 4; ks++) {
            const int kk = ks * 8;
            uint32_t af[2][4];
            #pragma unroll
            for (int mt = 0; mt < 2; mt++) {
                const int r = wm * 32 + mt * 16 + g;
                af[mt][0] = As[(kk + tg) * GLDA + r];
                af[mt][1] = As[(kk + tg) * GLDA + r + 8];
                af[mt][2] = As[(kk + tg + 4) * GLDA + r];
                af[mt][3] = As[(kk + tg + 4) * GLDA + r + 8];
            }
            #pragma unroll
            for (int nt = 0; nt < 8; nt++) {
                uint32_t bf[2];
                const int c = wn * 64 + nt * 8 + g;
                bf[0] = Bs[(kk + tg) * GLDB + c];
                bf[1] = Bs[(kk + tg + 4) * GLDB + c];
                mma_tf32(acc[0][nt], af[0], bf);
                mma_tf32(acc[1][nt], af[1], bf);
            }
        }
        __syncthreads();
    }

    #pragma unroll
    for (int mt = 0; mt < 2; mt++) {
        const int r_lo = row0 + wm * 32 + mt * 16 + g;
        const int r_hi = r_lo + 8;
        #pragma unroll
        for (int nt = 0; nt < 8; nt++) {
            const int c = col0 + wn * 64 + nt * 8 + 2 * tg;
            float2 v0 = make_float2(acc[mt][nt][0], acc[mt][nt][1]);
            float2 v1 = make_float2(acc[mt][nt][2], acc[mt][nt][3]);
            if (BIAS) {
                float2 bb = *(const float2*)&bias[c];
                v0.x += bb.x; v0.y += bb.y;
                v1.x += bb.x; v1.y += bb.y;
            }
            *(float2*)&C[(size_t)r_lo * N + c] = v0;
            *(float2*)&C[(size_t)r_hi * N + c] = v1;
        }
    }
}

// ---------------------------------------------------------------------------
// Flash attention with tf32 tensor cores.
// Block: 64 q-rows of one (b,h). 128 threads, 4 warps, 16 rows each.
// Kr[j][d], Vs[j][d] LD=72 (conflict-free B-frag reads), Ps[r][j] LD=68.
// Q fragments live in registers across the whole KV loop.
// ---------------------------------------------------------------------------
#define LDK 72
#define LDP 68
#define AT_SMEM ((2 * 64 * LDK + 64 * LDP) * (int)sizeof(uint32_t))

__global__ __launch_bounds__(128) void attn_tc(
    const float* __restrict__ qkv, float* __restrict__ out)
{
    extern __shared__ uint32_t sm[];
    uint32_t* Kr = sm;                   // [j][d]
    uint32_t* Vs = sm + 64 * LDK;        // [j][d]
    uint32_t* Ps = sm + 2 * 64 * LDK;    // [r][j] (also Q staging [r][d])

    const int tid  = threadIdx.x;
    const int lane = tid & 31;
    const int wid  = tid >> 5;
    const int g    = lane >> 2;
    const int tg   = lane & 3;
    const int qb   = blockIdx.x;         // 0..31
    const int bh   = blockIdx.y;         // 0..47
    const int b    = bh / H_;
    const int h    = bh % H_;

    const size_t base = (size_t)b * N_ * QKV_COLS;
    const int qoff = h * HD_;
    const int koff = D_ + h * HD_;
    const int voff = 2 * D_ + h * HD_;

    const int lr0 = tid >> 4;            // 0..7
    const int ld  = (tid & 15) * 4;      // 0..60

    // ---- stage Q (pre-scaled, tf32) into Ps as [r][d] ----
    #pragma unroll
    for (int rr = lr0; rr < 64; rr += 8) {
        float4 q = *(const float4*)&qkv[base + (size_t)(qb * 64 + rr) * QKV_COLS + qoff + ld];
        uint4 u = make_uint4(f2tf(q.x * 0.125f), f2tf(q.y * 0.125f),
                             f2tf(q.z * 0.125f), f2tf(q.w * 0.125f));
        *(uint4*)&Ps[rr * LDP + ld] = u;
    }
    __syncthreads();

    const int r_lo = wid * 16 + g;
    const int r_hi = r_lo + 8;

    // ---- Q fragments to registers (8 k-steps x 4 regs) ----
    uint32_t qf[8][4];
    #pragma unroll
    for (int ks = 0; ks < 8; ks++) {
        const int c = ks * 8 + tg;
        qf[ks][0] = Ps[r_lo * LDP + c];
        qf[ks][1] = Ps[r_hi * LDP + c];
        qf[ks][2] = Ps[r_lo * LDP + c + 4];
        qf[ks][3] = Ps[r_hi * LDP + c + 4];
    }

    float O[8][4];
    #pragma unroll
    for (int nt = 0; nt < 8; nt++)
        #pragma unroll
        for (int i = 0; i < 4; i++) O[nt][i] = 0.f;
    float m_lo = -INFINITY, m_hi = -INFINITY, l_lo = 0.f, l_hi = 0.f;

    for (int t = 0; t < N_ / 64; t++) {
        __syncthreads();   // prior readers of Kr/Vs done
        #pragma unroll
        for (int rr = lr0; rr < 64; rr += 8) {
            const size_t grow = base + (size_t)(t * 64 + rr) * QKV_COLS;
            float4 kk = *(const float4*)&qkv[grow + koff + ld];
            float4 vv = *(const float4*)&qkv[grow + voff + ld];
            *(uint4*)&Kr[rr * LDK + ld] = make_uint4(f2tf(kk.x), f2tf(kk.y), f2tf(kk.z), f2tf(kk.w));
            *(uint4*)&Vs[rr * LDK + ld] = make_uint4(f2tf(vv.x), f2tf(vv.y), f2tf(vv.z), f2tf(vv.w));
        }
        __syncthreads();

        // ---- S = Q @ K^T : B[k=d][n=j] = Kr[j][d] ----
        float s[8][4];
        #pragma unroll
        for (int nt = 0; nt < 8; nt++)
            #pragma unroll
            for (int i = 0; i < 4; i++) s[nt][i] = 0.f;

        #pragma unroll
        for (int ks = 0; ks < 8; ks++) {
            const int kk = ks * 8;
            #pragma unroll
            for (int nt = 0; nt < 8; nt++) {
                uint32_t bf[2];
                bf[0] = Kr[(nt * 8 + g) * LDK + kk + tg];
                bf[1] = Kr[(nt * 8 + g) * LDK + kk + tg + 4];
                mma_tf32(s[nt], qf[ks], bf);
            }
        }

        // ---- online softmax on fragments ----
        float rmx_lo = -INFINITY, rmx_hi = -INFINITY;
        #pragma unroll
        for (int nt = 0; nt < 8; nt++) {
            rmx_lo = fmaxf(rmx_lo, fmaxf(s[nt][0], s[nt][1]));
            rmx_hi = fmaxf(rmx_hi, fmaxf(s[nt][2], s[nt][3]));
        }
        rmx_lo = fmaxf(rmx_lo, __shfl_xor_sync(0xffffffffu, rmx_lo, 1));
        rmx_lo = fmaxf(rmx_lo, __shfl_xor_sync(0xffffffffu, rmx_lo, 2));
        rmx_hi = fmaxf(rmx_hi, __shfl_xor_sync(0xffffffffu, rmx_hi, 1));
        rmx_hi = fmaxf(rmx_hi, __shfl_xor_sync(0xffffffffu, rmx_hi, 2));

        const float mn_lo = fmaxf(m_lo, rmx_lo);
        const float mn_hi = fmaxf(m_hi, rmx_hi);
        const float sc_lo = __expf(m_lo - mn_lo);
        const float sc_hi = __expf(m_hi - mn_hi);

        float rs_lo = 0.f, rs_hi = 0.f;
        #pragma unroll
        for (int nt = 0; nt < 8; nt++) {
            s[nt][0] = __expf(s[nt][0] - mn_lo);
            s[nt][1] = __expf(s[nt][1] - mn_lo);
            s[nt][2] = __expf(s[nt][2] - mn_hi);
            s[nt][3] = __expf(s[nt][3] - mn_hi);
            rs_lo += s[nt][0] + s[nt][1];
            rs_hi += s[nt][2] + s[nt][3];
        }
        rs_lo += __shfl_xor_sync(0xffffffffu, rs_lo, 1);
        rs_lo += __shfl_xor_sync(0xffffffffu, rs_lo, 2);
        rs_hi += __shfl_xor_sync(0xffffffffu, rs_hi, 1);
        rs_hi += __shfl_xor_sync(0xffffffffu, rs_hi, 2);

        l_lo = l_lo * sc_lo + rs_lo;   m_lo = mn_lo;
        l_hi = l_hi * sc_hi + rs_hi;   m_hi = mn_hi;

        #pragma unroll
        for (int nt = 0; nt < 8; nt++) {
            O[nt][0] *= sc_lo; O[nt][1] *= sc_lo;
            O[nt][2] *= sc_hi; O[nt][3] *= sc_hi;
        }

        // ---- store P (tf32) to warp-private smem rows ----
        #pragma unroll
        for (int nt = 0; nt < 8; nt++) {
            const int c = nt * 8 + 2 * tg;
            Ps[r_lo * LDP + c]     = f2tf(s[nt][0]);
            Ps[r_lo * LDP + c + 1] = f2tf(s[nt][1]);
            Ps[r_hi * LDP + c]     = f2tf(s[nt][2]);
            Ps[r_hi * LDP + c + 1] = f2tf(s[nt][3]);
        }
        __syncwarp();

        // ---- O += P @ V : B[k=j][n=d] = Vs[j][d] ----
        #pragma unroll
        for (int ks = 0; ks < 8; ks++) {
            const int j0 = ks * 8;
            uint32_t pa[4];
            pa[0] = Ps[r_lo * LDP + j0 + tg];
            pa[1] = Ps[r_hi * LDP + j0 + tg];
            pa[2] = Ps[r_lo * LDP + j0 + tg + 4];
            pa[3] = Ps[r_hi * LDP + j0 + tg + 4];
            #pragma unroll
            for (int nt = 0; nt < 8; nt++) {
                uint32_t bv[2];
                bv[0] = Vs[(j0 + tg) * LDK + nt * 8 + g];
                bv[1] = Vs[(j0 + tg + 4) * LDK + nt * 8 + g];
                mma_tf32(O[nt], pa, bv);
            }
        }
    }

    // ---- finalize + write [B,N,D] ----
    const float il_lo = 1.f / l_lo;
    const float il_hi = 1.f / l_hi;
    const int n_lo = qb * 64 + r_lo;
    const int n_hi = n_lo + 8;
    #pragma unroll
    for (int nt = 0; nt < 8; nt++) {
        const int c = h * HD_ + nt * 8 + 2 * tg;
        float2 vlo = make_float2(O[nt][0] * il_lo, O[nt][1] * il_lo);
        float2 vhi = make_float2(O[nt][2] * il_hi, O[nt][3] * il_hi);
        *(float2*)&out[((size_t)b * N_ + n_lo) * D_ + c] = vlo;
        *(float2*)&out[((size_t)b * N_ + n_hi) * D_ + c] = vhi;
    }
}

// ---------------------------------------------------------------------------
// Launch
// ---------------------------------------------------------------------------
extern "C" void kernel_launch(void* const* d_in, const int* in_sizes, int n_in,
                              void* d_out, int out_size)
{
    const float* x      = (const float*)d_in[0];
    const float* w_qkv  = (const float*)d_in[1];
    const float* w_proj = (const float*)d_in[2];
    const float* b_proj = (const float*)d_in[3];
    float* out = (float*)d_out;

    float *qkv, *att;
    cudaGetSymbolAddress((void**)&qkv, g_qkv);
    cudaGetSymbolAddress((void**)&att, g_att);

    cudaFuncSetAttribute(attn_tc, cudaFuncAttributeMaxDynamicSharedMemorySize, AT_SMEM);

    // 1) QKV = X @ W_qkv : [8192,768] x [768,2304]
    gemm_tc<false><<<dim3(QKV_COLS / 128, M_ / 128), 256>>>(
        x, w_qkv, nullptr, qkv, M_, QKV_COLS, D_);

    // 2) fused flash attention -> [B,N,D]
    attn_tc<<<dim3(N_ / 64, B_ * H_), 128, AT_SMEM>>>(qkv, att);

    // 3) OUT = ATT @ W_proj + b : [8192,768] x [768,768]
    gemm_tc<true><<<dim3(D_ / 128, M_ / 128), 256>>>(
        att, w_proj, b_proj, out, M_, D_, D_);
}

// round 5
// speedup vs baseline: 2.6208x; 1.0650x over previous
#include <cuda_runtime.h>
#include <math.h>
#include <stdint.h>

// ---------------------------------------------------------------------------
// Problem constants
// ---------------------------------------------------------------------------
#define B_   4
#define N_   2048
#define D_   768
#define H_   12
#define HD_  64
#define M_   (B_ * N_)             // 8192
#define QKV_COLS (3 * D_)          // 2304

// Scratch (alloc-free rule)
__device__ float g_qkv[(size_t)M_ * QKV_COLS];
__device__ float g_att[(size_t)M_ * D_];

// ---------------------------------------------------------------------------
// tf32 helpers
// ---------------------------------------------------------------------------
__device__ __forceinline__ uint32_t f2tf(float x) {
    uint32_t r;
    asm("cvt.rna.tf32.f32 %0, %1;" : "=r"(r) : "f"(x));
    return r;
}

__device__ __forceinline__ void mma_tf32(float* c, const uint32_t* a, const uint32_t* b) {
    asm volatile(
        "mma.sync.aligned.m16n8k8.row.col.f32.tf32.tf32.f32 "
        "{%0,%1,%2,%3}, {%4,%5,%6,%7}, {%8,%9}, {%0,%1,%2,%3};"
        : "+f"(c[0]), "+f"(c[1]), "+f"(c[2]), "+f"(c[3])
        : "r"(a[0]), "r"(a[1]), "r"(a[2]), "r"(a[3]), "r"(b[0]), "r"(b[1]));
}

// ---------------------------------------------------------------------------
// tf32 tensor-core GEMM with register-prefetch pipelining.
// C[M,N] = A[M,K] @ B[K,N] (+bias). 128x128 block, BK=32, 256 threads.
// ---------------------------------------------------------------------------
#define GLDA 136
#define GLDB 136

template<bool BIAS>
__global__ __launch_bounds__(256) void gemm_tc(
    const float* __restrict__ A, const float* __restrict__ Bm,
    const float* __restrict__ bias, float* __restrict__ C,
    int M, int N, int K)
{
    __shared__ uint32_t As[32 * GLDA];   // transposed: As[k][m]
    __shared__ uint32_t Bs[32 * GLDB];   // Bs[k][n]

    const int tid  = threadIdx.x;
    const int lane = tid & 31;
    const int wid  = tid >> 5;
    const int g    = lane >> 2;
    const int tg   = lane & 3;
    const int wm   = wid & 3;
    const int wn   = wid >> 2;
    const int row0 = blockIdx.y * 128;
    const int col0 = blockIdx.x * 128;

    float acc[2][8][4];
    #pragma unroll
    for (int mt = 0; mt < 2; mt++)
        #pragma unroll
        for (int nt = 0; nt < 8; nt++)
            #pragma unroll
            for (int i = 0; i < 4; i++) acc[mt][nt][i] = 0.f;

    const int am  = tid & 127;
    const int akb = (tid >> 7) * 4;
    const int bk  = tid >> 3;
    const int bnb = (tid & 7) * 16;

    const float* Ap = A + (size_t)(row0 + am) * K;
    const float* Bp = Bm + (size_t)bk * N + col0;

    // prologue: prefetch tile 0
    float4 pa[4], pb[4];
    #pragma unroll
    for (int i = 0; i < 4; i++) {
        pa[i] = *(const float4*)(Ap + akb + i * 8);
        pb[i] = *(const float4*)(Bp + bnb + i * 4);
    }

    for (int k0 = 0; k0 < K; k0 += 32) {
        // store staged tile to smem (with tf32 convert)
        #pragma unroll
        for (int i = 0; i < 4; i++) {
            const int k = akb + i * 8;
            As[(k + 0) * GLDA + am] = f2tf(pa[i].x);
            As[(k + 1) * GLDA + am] = f2tf(pa[i].y);
            As[(k + 2) * GLDA + am] = f2tf(pa[i].z);
            As[(k + 3) * GLDA + am] = f2tf(pa[i].w);
            const int n = bnb + i * 4;
            uint4 u = make_uint4(f2tf(pb[i].x), f2tf(pb[i].y), f2tf(pb[i].z), f2tf(pb[i].w));
            *(uint4*)&Bs[bk * GLDB + n] = u;
        }
        __syncthreads();

        // prefetch next tile (LDG latency overlaps the mma phase)
        if (k0 + 32 < K) {
            #pragma unroll
            for (int i = 0; i < 4; i++) {
                pa[i] = *(const float4*)(Ap + k0 + 32 + akb + i * 8);
                pb[i] = *(const float4*)(Bp + (size_t)(k0 + 32) * N + bnb + i * 4);
            }
        }

        #pragma unroll
        for (int ks = 0; ks < 4; ks++) {
            const int kk = ks * 8;
            uint32_t af[2][4];
            #pragma unroll
            for (int mt = 0; mt < 2; mt++) {
                const int r = wm * 32 + mt * 16 + g;
                af[mt][0] = As[(kk + tg) * GLDA + r];
                af[mt][1] = As[(kk + tg) * GLDA + r + 8];
                af[mt][2] = As[(kk + tg + 4) * GLDA + r];
                af[mt][3] = As[(kk + tg + 4) * GLDA + r + 8];
            }
            #pragma unroll
            for (int nt = 0; nt < 8; nt++) {
                uint32_t bf[2];
                const int c = wn * 64 + nt * 8 + g;
                bf[0] = Bs[(kk + tg) * GLDB + c];
                bf[1] = Bs[(kk + tg + 4) * GLDB + c];
                mma_tf32(acc[0][nt], af[0], bf);
                mma_tf32(acc[1][nt], af[1], bf);
            }
        }
        __syncthreads();
    }

    #pragma unroll
    for (int mt = 0; mt < 2; mt++) {
        const int r_lo = row0 + wm * 32 + mt * 16 + g;
        const int r_hi = r_lo + 8;
        #pragma unroll
        for (int nt = 0; nt < 8; nt++) {
            const int c = col0 + wn * 64 + nt * 8 + 2 * tg;
            float2 v0 = make_float2(acc[mt][nt][0], acc[mt][nt][1]);
            float2 v1 = make_float2(acc[mt][nt][2], acc[mt][nt][3]);
            if (BIAS) {
                float2 bb = *(const float2*)&bias[c];
                v0.x += bb.x; v0.y += bb.y;
                v1.x += bb.x; v1.y += bb.y;
            }
            *(float2*)&C[(size_t)r_lo * N + c] = v0;
            *(float2*)&C[(size_t)r_hi * N + c] = v1;
        }
    }
}

// ---------------------------------------------------------------------------
// Flash attention, tf32 tensor cores, register-prefetched K/V.
// Block: 128 q-rows of one (b,h). 256 threads, 8 warps, 16 rows/warp.
// Qs[r][d] LDP, Ps[r][j] LDP, Kr[j][d] LDKK (bank: g*4+tg, conflict-free),
// Vs[j][d] LDVV (bank: tg*8+g, conflict-free).
// ---------------------------------------------------------------------------
#define LDP  68
#define LDKK 68
#define LDVV 72
#define QROWS 128
#define AT_SMEM ((2 * QROWS * LDP + 64 * LDKK + 64 * LDVV) * (int)sizeof(uint32_t))

__global__ __launch_bounds__(256) void attn_tc(
    const float* __restrict__ qkv, float* __restrict__ out)
{
    extern __shared__ uint32_t sm[];
    uint32_t* Qs = sm;                              // [r][d] 128 x LDP
    uint32_t* Ps = sm + QROWS * LDP;                // [r][j] 128 x LDP
    uint32_t* Kr = sm + 2 * QROWS * LDP;            // [j][d] 64 x LDKK
    uint32_t* Vs = sm + 2 * QROWS * LDP + 64 * LDKK;// [j][d] 64 x LDVV

    const int tid  = threadIdx.x;
    const int lane = tid & 31;
    const int wid  = tid >> 5;
    const int g    = lane >> 2;
    const int tg   = lane & 3;
    const int qb   = blockIdx.x;         // 0..15
    const int bh   = blockIdx.y;         // 0..47
    const int b    = bh / H_;
    const int h    = bh % H_;

    const size_t base = (size_t)b * N_ * QKV_COLS;
    const int qoff = h * HD_;
    const int koff = D_ + h * HD_;
    const int voff = 2 * D_ + h * HD_;

    const int lr0 = tid >> 4;            // 0..15
    const int ld  = (tid & 15) * 4;      // 0..60

    // ---- prefetch K/V tile 0 into registers ----
    float4 pk[4], pv[4];
    #pragma unroll
    for (int i = 0; i < 4; i++) {
        const size_t grow = base + (size_t)(lr0 + i * 16) * QKV_COLS;
        pk[i] = *(const float4*)&qkv[grow + koff + ld];
        pv[i] = *(const float4*)&qkv[grow + voff + ld];
    }

    // ---- stage Q (pre-scaled, tf32) into Qs ----
    #pragma unroll
    for (int i = 0; i < 8; i++) {
        const int rr = lr0 + i * 16;
        float4 q = *(const float4*)&qkv[base + (size_t)(qb * QROWS + rr) * QKV_COLS + qoff + ld];
        uint4 u = make_uint4(f2tf(q.x * 0.125f), f2tf(q.y * 0.125f),
                             f2tf(q.z * 0.125f), f2tf(q.w * 0.125f));
        *(uint4*)&Qs[rr * LDP + ld] = u;
    }
    __syncthreads();

    const int r_lo = wid * 16 + g;
    const int r_hi = r_lo + 8;

    float O[8][4];
    #pragma unroll
    for (int nt = 0; nt < 8; nt++)
        #pragma unroll
        for (int i = 0; i < 4; i++) O[nt][i] = 0.f;
    float m_lo = -INFINITY, m_hi = -INFINITY, l_lo = 0.f, l_hi = 0.f;

    for (int t = 0; t < N_ / 64; t++) {
        // store staged K/V tile to smem
        #pragma unroll
        for (int i = 0; i < 4; i++) {
            const int rr = lr0 + i * 16;
            *(uint4*)&Kr[rr * LDKK + ld] = make_uint4(f2tf(pk[i].x), f2tf(pk[i].y), f2tf(pk[i].z), f2tf(pk[i].w));
            *(uint4*)&Vs[rr * LDVV + ld] = make_uint4(f2tf(pv[i].x), f2tf(pv[i].y), f2tf(pv[i].z), f2tf(pv[i].w));
        }
        __syncthreads();

        // prefetch next K/V tile (overlaps with compute below)
        if (t + 1 < N_ / 64) {
            #pragma unroll
            for (int i = 0; i < 4; i++) {
                const size_t grow = base + (size_t)((t + 1) * 64 + lr0 + i * 16) * QKV_COLS;
                pk[i] = *(const float4*)&qkv[grow + koff + ld];
                pv[i] = *(const float4*)&qkv[grow + voff + ld];
            }
        }

        // ---- S = Q @ K^T ----
        float s[8][4];
        #pragma unroll
        for (int nt = 0; nt < 8; nt++)
            #pragma unroll
            for (int i = 0; i < 4; i++) s[nt][i] = 0.f;

        #pragma unroll
        for (int ks = 0; ks < 8; ks++) {
            const int kk = ks * 8;
            uint32_t qf[4];
            qf[0] = Qs[r_lo * LDP + kk + tg];
            qf[1] = Qs[r_hi * LDP + kk + tg];
            qf[2] = Qs[r_lo * LDP + kk + tg + 4];
            qf[3] = Qs[r_hi * LDP + kk + tg + 4];
            #pragma unroll
            for (int nt = 0; nt < 8; nt++) {
                uint32_t bf[2];
                bf[0] = Kr[(nt * 8 + g) * LDKK + kk + tg];
                bf[1] = Kr[(nt * 8 + g) * LDKK + kk + tg + 4];
                mma_tf32(s[nt], qf, bf);
            }
        }

        // ---- online softmax on fragments ----
        float rmx_lo = -INFINITY, rmx_hi = -INFINITY;
        #pragma unroll
        for (int nt = 0; nt < 8; nt++) {
            rmx_lo = fmaxf(rmx_lo, fmaxf(s[nt][0], s[nt][1]));
            rmx_hi = fmaxf(rmx_hi, fmaxf(s[nt][2], s[nt][3]));
        }
        rmx_lo = fmaxf(rmx_lo, __shfl_xor_sync(0xffffffffu, rmx_lo, 1));
        rmx_lo = fmaxf(rmx_lo, __shfl_xor_sync(0xffffffffu, rmx_lo, 2));
        rmx_hi = fmaxf(rmx_hi, __shfl_xor_sync(0xffffffffu, rmx_hi, 1));
        rmx_hi = fmaxf(rmx_hi, __shfl_xor_sync(0xffffffffu, rmx_hi, 2));

        const float mn_lo = fmaxf(m_lo, rmx_lo);
        const float mn_hi = fmaxf(m_hi, rmx_hi);
        const float sc_lo = __expf(m_lo - mn_lo);
        const float sc_hi = __expf(m_hi - mn_hi);

        float rs_lo = 0.f, rs_hi = 0.f;
        #pragma unroll
        for (int nt = 0; nt < 8; nt++) {
            s[nt][0] = __expf(s[nt][0] - mn_lo);
            s[nt][1] = __expf(s[nt][1] - mn_lo);
            s[nt][2] = __expf(s[nt][2] - mn_hi);
            s[nt][3] = __expf(s[nt][3] - mn_hi);
            rs_lo += s[nt][0] + s[nt][1];
            rs_hi += s[nt][2] + s[nt][3];
        }
        rs_lo += __shfl_xor_sync(0xffffffffu, rs_lo, 1);
        rs_lo += __shfl_xor_sync(0xffffffffu, rs_lo, 2);
        rs_hi += __shfl_xor_sync(0xffffffffu, rs_hi, 1);
        rs_hi += __shfl_xor_sync(0xffffffffu, rs_hi, 2);

        l_lo = l_lo * sc_lo + rs_lo;   m_lo = mn_lo;
        l_hi = l_hi * sc_hi + rs_hi;   m_hi = mn_hi;

        #pragma unroll
        for (int nt = 0; nt < 8; nt++) {
            O[nt][0] *= sc_lo; O[nt][1] *= sc_lo;
            O[nt][2] *= sc_hi; O[nt][3] *= sc_hi;
        }

        // ---- store P (tf32) to warp-private smem rows ----
        #pragma unroll
        for (int nt = 0; nt < 8; nt++) {
            const int c = nt * 8 + 2 * tg;
            Ps[r_lo * LDP + c]     = f2tf(s[nt][0]);
            Ps[r_lo * LDP + c + 1] = f2tf(s[nt][1]);
            Ps[r_hi * LDP + c]     = f2tf(s[nt][2]);
            Ps[r_hi * LDP + c + 1] = f2tf(s[nt][3]);
        }
        __syncwarp();

        // ---- O += P @ V ----
        #pragma unroll
        for (int ks = 0; ks < 8; ks++) {
            const int j0 = ks * 8;
            uint32_t pa2[4];
            pa2[0] = Ps[r_lo * LDP + j0 + tg];
            pa2[1] = Ps[r_hi * LDP + j0 + tg];
            pa2[2] = Ps[r_lo * LDP + j0 + tg + 4];
            pa2[3] = Ps[r_hi * LDP + j0 + tg + 4];
            #pragma unroll
            for (int nt = 0; nt < 8; nt++) {
                uint32_t bv[2];
                bv[0] = Vs[(j0 + tg) * LDVV + nt * 8 + g];
                bv[1] = Vs[(j0 + tg + 4) * LDVV + nt * 8 + g];
                mma_tf32(O[nt], pa2, bv);
            }
        }
        __syncthreads();   // guard Kr/Vs overwrite next iter
    }

    // ---- finalize + write [B,N,D] ----
    const float il_lo = 1.f / l_lo;
    const float il_hi = 1.f / l_hi;
    const int n_lo = qb * QROWS + r_lo;
    const int n_hi = n_lo + 8;
    #pragma unroll
    for (int nt = 0; nt < 8; nt++) {
        const int c = h * HD_ + nt * 8 + 2 * tg;
        float2 vlo = make_float2(O[nt][0] * il_lo, O[nt][1] * il_lo);
        float2 vhi = make_float2(O[nt][2] * il_hi, O[nt][3] * il_hi);
        *(float2*)&out[((size_t)b * N_ + n_lo) * D_ + c] = vlo;
        *(float2*)&out[((size_t)b * N_ + n_hi) * D_ + c] = vhi;
    }
}

// ---------------------------------------------------------------------------
// Launch
// ---------------------------------------------------------------------------
extern "C" void kernel_launch(void* const* d_in, const int* in_sizes, int n_in,
                              void* d_out, int out_size)
{
    const float* x      = (const float*)d_in[0];
    const float* w_qkv  = (const float*)d_in[1];
    const float* w_proj = (const float*)d_in[2];
    const float* b_proj = (const float*)d_in[3];
    float* out = (float*)d_out;

    float *qkv, *att;
    cudaGetSymbolAddress((void**)&qkv, g_qkv);
    cudaGetSymbolAddress((void**)&att, g_att);

    cudaFuncSetAttribute(attn_tc, cudaFuncAttributeMaxDynamicSharedMemorySize, AT_SMEM);

    // 1) QKV = X @ W_qkv : [8192,768] x [768,2304]
    gemm_tc<false><<<dim3(QKV_COLS / 128, M_ / 128), 256>>>(
        x, w_qkv, nullptr, qkv, M_, QKV_COLS, D_);

    // 2) fused flash attention -> [B,N,D]
    attn_tc<<<dim3(N_ / QROWS, B_ * H_), 256, AT_SMEM>>>(qkv, att);

    // 3) OUT = ATT @ W_proj + b : [8192,768] x [768,768]
    gemm_tc<true><<<dim3(D_ / 128, M_ / 128), 256>>>(
        att, w_proj, b_proj, out, M_, D_, D_);
}

// round 7
// speedup vs baseline: 3.1705x; 1.2098x over previous
#include <cuda_runtime.h>
#include <math.h>
#include <stdint.h>

// ---------------------------------------------------------------------------
// Problem constants
// ---------------------------------------------------------------------------
#define B_   4
#define N_   2048
#define D_   768
#define H_   12
#define HD_  64
#define M_   (B_ * N_)             // 8192
#define QKV_COLS (3 * D_)          // 2304

// Scratch (alloc-free rule)
__device__ float g_qkv[(size_t)M_ * QKV_COLS];
__device__ float g_att[(size_t)M_ * D_];
__device__ float g_wqkvT[(size_t)QKV_COLS * D_];   // [N=2304][K=768]
__device__ float g_wprojT[(size_t)D_ * D_];        // [N=768][K=768]

// ---------------------------------------------------------------------------
// tf32 helpers (legacy mma path — harness targets sm_100 base, no tcgen05)
// ---------------------------------------------------------------------------
__device__ __forceinline__ uint32_t f2tf(float x) {
    uint32_t r;
    asm("cvt.rna.tf32.f32 %0, %1;" : "=r"(r) : "f"(x));
    return r;
}

__device__ __forceinline__ void mma_tf32(float* c, const uint32_t* a, const uint32_t* b) {
    asm volatile(
        "mma.sync.aligned.m16n8k8.row.col.f32.tf32.tf32.f32 "
        "{%0,%1,%2,%3}, {%4,%5,%6,%7}, {%8,%9}, {%0,%1,%2,%3};"
        : "+f"(c[0]), "+f"(c[1]), "+f"(c[2]), "+f"(c[3])
        : "r"(a[0]), "r"(a[1]), "r"(a[2]), "r"(a[3]), "r"(b[0]), "r"(b[1]));
}

// ---------------------------------------------------------------------------
// Weight transpose: out[N][K] = in[K][N]
// ---------------------------------------------------------------------------
__global__ __launch_bounds__(256) void transpose_k(
    const float* __restrict__ in, float* __restrict__ out, int K, int N)
{
    __shared__ float t[32][33];
    const int kb = blockIdx.y * 32, nb = blockIdx.x * 32;
    const int x = threadIdx.x, y = threadIdx.y;
    #pragma unroll
    for (int i = 0; i < 32; i += 8)
        t[y + i][x] = in[(size_t)(kb + y + i) * N + nb + x];
    __syncthreads();
    #pragma unroll
    for (int i = 0; i < 32; i += 8)
        out[(size_t)(nb + y + i) * K + kb + x] = t[x][y + i];
}

// ---------------------------------------------------------------------------
// tf32 GEMM, fragment-major smem + 2-stage pipeline.
// C[M,N] = A[M,K] @ WT[N,K]^T (+bias). 128x128 CTA tile, BK=32, 256 threads,
// 8 warps each 32x64. Both A and WT are K-major -> identical tile handling.
//
// smem (floats): plane(ks) = 1032 floats; tile = 4 planes = 4128 floats.
//   layout inside plane: [row 0..127] stride 8, entries {x[k8+tg], x[k8+tg+4]}
//   as float2 at word offset row*8 + tg*2 (+sec).
//   Fragment LDS.64 reads are conflict-free per half-warp phase.
// stages: A0@0 B0@4128 A1@8256 B1@12384  -> 16512 floats = 66048 B dynamic.
// ---------------------------------------------------------------------------
#define FF_SMEM (16512 * 4)

template<bool BIAS>
__global__ __launch_bounds__(256, 2) void gemm_ff(
    const float* __restrict__ A, const float* __restrict__ WT,
    const float* __restrict__ bias, float* __restrict__ C,
    int N, int K)
{
    extern __shared__ float smf[];

    const int tid  = threadIdx.x;
    const int lane = tid & 31;
    const int wid  = tid >> 5;
    const int g    = lane >> 2;
    const int tg   = lane & 3;
    const int wm   = wid & 3;
    const int wn   = wid >> 2;
    const int row0 = blockIdx.y * 128;
    const int col0 = blockIdx.x * 128;
    const int KT   = K / 32;

    float acc[2][8][4];
    #pragma unroll
    for (int mt = 0; mt < 2; mt++)
        #pragma unroll
        for (int nt = 0; nt < 8; nt++)
            #pragma unroll
            for (int i = 0; i < 4; i++) acc[mt][nt][i] = 0.f;

    // global load mapping: thread covers rows lrow+32i (i=0..3),
    // k-pair (8*ks0 + 2*m0, +4) as two LDG.64
    const int lrow = tid >> 3;           // 0..31
    const int lkq  = tid & 7;
    const int ks0  = lkq >> 1;
    const int m0   = lkq & 1;
    const int kA   = 8 * ks0 + 2 * m0;

    const float* Ap = A  + (size_t)(row0 + lrow) * K + kA;
    const float* Bp = WT + (size_t)(col0 + lrow) * K + kA;

    // staging regs: [matrix(0=A,1=B)][i][pair]
    float2 rg[2][4][2];

    #define LOAD_TILE(t_) do {                                               \
        const size_t koff_ = (size_t)(t_) * 32;                             \
        _Pragma("unroll")                                                    \
        for (int i_ = 0; i_ < 4; i_++) {                                     \
            const float* a_ = Ap + (size_t)(i_ * 32) * K + koff_;            \
            const float* b_ = Bp + (size_t)(i_ * 32) * K + koff_;            \
            rg[0][i_][0] = *(const float2*)a_;                               \
            rg[0][i_][1] = *(const float2*)(a_ + 4);                         \
            rg[1][i_][0] = *(const float2*)b_;                               \
            rg[1][i_][1] = *(const float2*)(b_ + 4);                         \
        }                                                                    \
    } while (0)

    #define STORE_TILE(s_) do {                                              \
        float* baseA_ = smf + (s_) * 8256 + ks0 * 1032 + 4 * m0;             \
        float* baseB_ = baseA_ + 4128;                                       \
        _Pragma("unroll")                                                    \
        for (int i_ = 0; i_ < 4; i_++) {                                     \
            const int r_ = lrow + 32 * i_;                                   \
            uint4 pa_ = make_uint4(f2tf(rg[0][i_][0].x), f2tf(rg[0][i_][1].x),\
                                   f2tf(rg[0][i_][0].y), f2tf(rg[0][i_][1].y));\
            uint4 pb_ = make_uint4(f2tf(rg[1][i_][0].x), f2tf(rg[1][i_][1].x),\
                                   f2tf(rg[1][i_][0].y), f2tf(rg[1][i_][1].y));\
            *(uint4*)(baseA_ + r_ * 8) = pa_;                                \
            *(uint4*)(baseB_ + r_ * 8) = pb_;                                \
        }                                                                    \
    } while (0)

    // prologue
    LOAD_TILE(0);
    STORE_TILE(0);
    if (KT > 1) LOAD_TILE(1);
    __syncthreads();

    for (int t = 0; t < KT; t++) {
        const int s = t & 1;

        // stage t+1 into the other buffer; prefetch t+2 (overlaps mma below)
        if (t + 1 < KT) {
            STORE_TILE(s ^ 1);
            if (t + 2 < KT) LOAD_TILE(t + 2);
        }

        const float2* As2 = (const float2*)(smf + s * 8256);
        const float2* Bs2 = (const float2*)(smf + s * 8256 + 4128);

        #pragma unroll
        for (int ks = 0; ks < 4; ks++) {
            const float2* Ak = As2 + ks * 516;
            const float2* Bk = Bs2 + ks * 516;
            uint32_t af[2][4];
            #pragma unroll
            for (int mt = 0; mt < 2; mt++) {
                const int r = wm * 32 + mt * 16 + g;
                float2 v1 = Ak[r * 4 + tg];
                float2 v2 = Ak[(r + 8) * 4 + tg];
                af[mt][0] = __float_as_uint(v1.x);
                af[mt][1] = __float_as_uint(v2.x);
                af[mt][2] = __float_as_uint(v1.y);
                af[mt][3] = __float_as_uint(v2.y);
            }
            #pragma unroll
            for (int nt = 0; nt < 8; nt++) {
                const int c = wn * 64 + nt * 8 + g;
                float2 w = Bk[c * 4 + tg];
                uint32_t bf[2] = { __float_as_uint(w.x), __float_as_uint(w.y) };
                mma_tf32(acc[0][nt], af[0], bf);
                mma_tf32(acc[1][nt], af[1], bf);
            }
        }
        __syncthreads();
    }

    #undef LOAD_TILE
    #undef STORE_TILE

    #pragma unroll
    for (int mt = 0; mt < 2; mt++) {
        const int r_lo = row0 + wm * 32 + mt * 16 + g;
        const int r_hi = r_lo + 8;
        #pragma unroll
        for (int nt = 0; nt < 8; nt++) {
            const int c = col0 + wn * 64 + nt * 8 + 2 * tg;
            float2 v0 = make_float2(acc[mt][nt][0], acc[mt][nt][1]);
            float2 v1 = make_float2(acc[mt][nt][2], acc[mt][nt][3]);
            if (BIAS) {
                float2 bb = *(const float2*)&bias[c];
                v0.x += bb.x; v0.y += bb.y;
                v1.x += bb.x; v1.y += bb.y;
            }
            *(float2*)&C[(size_t)r_lo * N + c] = v0;
            *(float2*)&C[(size_t)r_hi * N + c] = v1;
        }
    }
}

// ---------------------------------------------------------------------------
// Flash attention, tf32 legacy mma (unchanged from the 1004us kernel).
// ---------------------------------------------------------------------------
#define LDP  68
#define LDKK 68
#define LDVV 72
#define QROWS 128
#define AT_SMEM ((2 * QROWS * LDP + 64 * LDKK + 64 * LDVV) * (int)sizeof(uint32_t))

__global__ __launch_bounds__(256) void attn_tc(
    const float* __restrict__ qkv, float* __restrict__ out)
{
    extern __shared__ uint32_t sm[];
    uint32_t* Qs = sm;
    uint32_t* Ps = sm + QROWS * LDP;
    uint32_t* Kr = sm + 2 * QROWS * LDP;
    uint32_t* Vs = sm + 2 * QROWS * LDP + 64 * LDKK;

    const int tid  = threadIdx.x;
    const int lane = tid & 31;
    const int wid  = tid >> 5;
    const int g    = lane >> 2;
    const int tg   = lane & 3;
    const int qb   = blockIdx.x;
    const int bh   = blockIdx.y;
    const int b    = bh / H_;
    const int h    = bh % H_;

    const size_t base = (size_t)b * N_ * QKV_COLS;
    const int qoff = h * HD_;
    const int koff = D_ + h * HD_;
    const int voff = 2 * D_ + h * HD_;

    const int lr0 = tid >> 4;
    const int ld  = (tid & 15) * 4;

    float4 pk[4], pv[4];
    #pragma unroll
    for (int i = 0; i < 4; i++) {
        const size_t grow = base + (size_t)(lr0 + i * 16) * QKV_COLS;
        pk[i] = *(const float4*)&qkv[grow + koff + ld];
        pv[i] = *(const float4*)&qkv[grow + voff + ld];
    }

    #pragma unroll
    for (int i = 0; i < 8; i++) {
        const int rr = lr0 + i * 16;
        float4 q = *(const float4*)&qkv[base + (size_t)(qb * QROWS + rr) * QKV_COLS + qoff + ld];
        uint4 u = make_uint4(f2tf(q.x * 0.125f), f2tf(q.y * 0.125f),
                             f2tf(q.z * 0.125f), f2tf(q.w * 0.125f));
        *(uint4*)&Qs[rr * LDP + ld] = u;
    }
    __syncthreads();

    const int r_lo = wid * 16 + g;
    const int r_hi = r_lo + 8;

    float O[8][4];
    #pragma unroll
    for (int nt = 0; nt < 8; nt++)
        #pragma unroll
        for (int i = 0; i < 4; i++) O[nt][i] = 0.f;
    float m_lo = -INFINITY, m_hi = -INFINITY, l_lo = 0.f, l_hi = 0.f;

    for (int t = 0; t < N_ / 64; t++) {
        #pragma unroll
        for (int i = 0; i < 4; i++) {
            const int rr = lr0 + i * 16;
            *(uint4*)&Kr[rr * LDKK + ld] = make_uint4(f2tf(pk[i].x), f2tf(pk[i].y), f2tf(pk[i].z), f2tf(pk[i].w));
            *(uint4*)&Vs[rr * LDVV + ld] = make_uint4(f2tf(pv[i].x), f2tf(pv[i].y), f2tf(pv[i].z), f2tf(pv[i].w));
        }
        __syncthreads();

        if (t + 1 < N_ / 64) {
            #pragma unroll
            for (int i = 0; i < 4; i++) {
                const size_t grow = base + (size_t)((t + 1) * 64 + lr0 + i * 16) * QKV_COLS;
                pk[i] = *(const float4*)&qkv[grow + koff + ld];
                pv[i] = *(const float4*)&qkv[grow + voff + ld];
            }
        }

        float s[8][4];
        #pragma unroll
        for (int nt = 0; nt < 8; nt++)
            #pragma unroll
            for (int i = 0; i < 4; i++) s[nt][i] = 0.f;

        #pragma unroll
        for (int ks = 0; ks < 8; ks++) {
            const int kk = ks * 8;
            uint32_t qf[4];
            qf[0] = Qs[r_lo * LDP + kk + tg];
            qf[1] = Qs[r_hi * LDP + kk + tg];
            qf[2] = Qs[r_lo * LDP + kk + tg + 4];
            qf[3] = Qs[r_hi * LDP + kk + tg + 4];
            #pragma unroll
            for (int nt = 0; nt < 8; nt++) {
                uint32_t bf[2];
                bf[0] = Kr[(nt * 8 + g) * LDKK + kk + tg];
                bf[1] = Kr[(nt * 8 + g) * LDKK + kk + tg + 4];
                mma_tf32(s[nt], qf, bf);
            }
        }

        float rmx_lo = -INFINITY, rmx_hi = -INFINITY;
        #pragma unroll
        for (int nt = 0; nt < 8; nt++) {
            rmx_lo = fmaxf(rmx_lo, fmaxf(s[nt][0], s[nt][1]));
            rmx_hi = fmaxf(rmx_hi, fmaxf(s[nt][2], s[nt][3]));
        }
        rmx_lo = fmaxf(rmx_lo, __shfl_xor_sync(0xffffffffu, rmx_lo, 1));
        rmx_lo = fmaxf(rmx_lo, __shfl_xor_sync(0xffffffffu, rmx_lo, 2));
        rmx_hi = fmaxf(rmx_hi, __shfl_xor_sync(0xffffffffu, rmx_hi, 1));
        rmx_hi = fmaxf(rmx_hi, __shfl_xor_sync(0xffffffffu, rmx_hi, 2));

        const float mn_lo = fmaxf(m_lo, rmx_lo);
        const float mn_hi = fmaxf(m_hi, rmx_hi);
        const float sc_lo = __expf(m_lo - mn_lo);
        const float sc_hi = __expf(m_hi - mn_hi);

        float rs_lo = 0.f, rs_hi = 0.f;
        #pragma unroll
        for (int nt = 0; nt < 8; nt++) {
            s[nt][0] = __expf(s[nt][0] - mn_lo);
            s[nt][1] = __expf(s[nt][1] - mn_lo);
            s[nt][2] = __expf(s[nt][2] - mn_hi);
            s[nt][3] = __expf(s[nt][3] - mn_hi);
            rs_lo += s[nt][0] + s[nt][1];
            rs_hi += s[nt][2] + s[nt][3];
        }
        rs_lo += __shfl_xor_sync(0xffffffffu, rs_lo, 1);
        rs_lo += __shfl_xor_sync(0xffffffffu, rs_lo, 2);
        rs_hi += __shfl_xor_sync(0xffffffffu, rs_hi, 1);
        rs_hi += __shfl_xor_sync(0xffffffffu, rs_hi, 2);

        l_lo = l_lo * sc_lo + rs_lo;   m_lo = mn_lo;
        l_hi = l_hi * sc_hi + rs_hi;   m_hi = mn_hi;

        #pragma unroll
        for (int nt = 0; nt < 8; nt++) {
            O[nt][0] *= sc_lo; O[nt][1] *= sc_lo;
            O[nt][2] *= sc_hi; O[nt][3] *= sc_hi;
        }

        #pragma unroll
        for (int nt = 0; nt < 8; nt++) {
            const int c = nt * 8 + 2 * tg;
            Ps[r_lo * LDP + c]     = f2tf(s[nt][0]);
            Ps[r_lo * LDP + c + 1] = f2tf(s[nt][1]);
            Ps[r_hi * LDP + c]     = f2tf(s[nt][2]);
            Ps[r_hi * LDP + c + 1] = f2tf(s[nt][3]);
        }
        __syncwarp();

        #pragma unroll
        for (int ks = 0; ks < 8; ks++) {
            const int j0 = ks * 8;
            uint32_t pa2[4];
            pa2[0] = Ps[r_lo * LDP + j0 + tg];
            pa2[1] = Ps[r_hi * LDP + j0 + tg];
            pa2[2] = Ps[r_lo * LDP + j0 + tg + 4];
            pa2[3] = Ps[r_hi * LDP + j0 + tg + 4];
            #pragma unroll
            for (int nt = 0; nt < 8; nt++) {
                uint32_t bv[2];
                bv[0] = Vs[(j0 + tg) * LDVV + nt * 8 + g];
                bv[1] = Vs[(j0 + tg + 4) * LDVV + nt * 8 + g];
                mma_tf32(O[nt], pa2, bv);
            }
        }
        __syncthreads();
    }

    const float il_lo = 1.f / l_lo;
    const float il_hi = 1.f / l_hi;
    const int n_lo = qb * QROWS + r_lo;
    const int n_hi = n_lo + 8;
    #pragma unroll
    for (int nt = 0; nt < 8; nt++) {
        const int c = h * HD_ + nt * 8 + 2 * tg;
        float2 vlo = make_float2(O[nt][0] * il_lo, O[nt][1] * il_lo);
        float2 vhi = make_float2(O[nt][2] * il_hi, O[nt][3] * il_hi);
        *(float2*)&out[((size_t)b * N_ + n_lo) * D_ + c] = vlo;
        *(float2*)&out[((size_t)b * N_ + n_hi) * D_ + c] = vhi;
    }
}

// ---------------------------------------------------------------------------
// Launch
// ---------------------------------------------------------------------------
extern "C" void kernel_launch(void* const* d_in, const int* in_sizes, int n_in,
                              void* d_out, int out_size)
{
    const float* x      = (const float*)d_in[0];
    const float* w_qkv  = (const float*)d_in[1];
    const float* w_proj = (const float*)d_in[2];
    const float* b_proj = (const float*)d_in[3];
    float* out = (float*)d_out;

    float *qkv, *att, *wqkvT, *wprojT;
    cudaGetSymbolAddress((void**)&qkv, g_qkv);
    cudaGetSymbolAddress((void**)&att, g_att);
    cudaGetSymbolAddress((void**)&wqkvT, g_wqkvT);
    cudaGetSymbolAddress((void**)&wprojT, g_wprojT);

    cudaFuncSetAttribute(attn_tc, cudaFuncAttributeMaxDynamicSharedMemorySize, AT_SMEM);
    cudaFuncSetAttribute(gemm_ff<false>, cudaFuncAttributeMaxDynamicSharedMemorySize, FF_SMEM);
    cudaFuncSetAttribute(gemm_ff<true>,  cudaFuncAttributeMaxDynamicSharedMemorySize, FF_SMEM);

    // 0) transpose weights to K-major: WT[n][k] = W[k][n]
    transpose_k<<<dim3(QKV_COLS / 32, D_ / 32), dim3(32, 8)>>>(w_qkv, wqkvT, D_, QKV_COLS);
    transpose_k<<<dim3(D_ / 32, D_ / 32), dim3(32, 8)>>>(w_proj, wprojT, D_, D_);

    // 1) QKV = X @ W_qkv
    gemm_ff<false><<<dim3(QKV_COLS / 128, M_ / 128), 256, FF_SMEM>>>(
        x, wqkvT, nullptr, qkv, QKV_COLS, D_);

    // 2) fused flash attention -> [B,N,D]
    attn_tc<<<dim3(N_ / QROWS, B_ * H_), 256, AT_SMEM>>>(qkv, att);

    // 3) OUT = ATT @ W_proj + b
    gemm_ff<true><<<dim3(D_ / 128, M_ / 128), 256, FF_SMEM>>>(
        att, wprojT, b_proj, out, D_, D_);
}